// round 13
// baseline (speedup 1.0000x reference)
#include <cuda_runtime.h>
#include <cuda_bf16.h>
#include <math.h>
#include <stdint.h>

#define B_ 4096
#define S_ 50
#define I_ 4
#define E_ 64

#define NCHUNK 4
#define BCHUNK (B_ / NCHUNK)     // 1024 b per chunk

// hat scratch, layout (S, B, I*E): hat2[s][b][m] — fp32, 209.7 MB
__device__ __align__(256) float g_hat[(size_t)S_ * B_ * I_ * E_];

// pre-split bf16 hi/lo copies of w
#define W_N ((size_t)S_ * I_ * E_ * E_)  // 819,200
__device__ __align__(256) __nv_bfloat16 g_w_h[W_N];
__device__ __align__(256) __nv_bfloat16 g_w_l[W_N];

// ============================================================================
// helpers
// ============================================================================
__device__ __forceinline__ uint32_t smem_u32(const void* p) {
    uint32_t a;
    asm("{ .reg .u64 t; cvta.to.shared.u64 t, %1; cvt.u32.u64 %0, t; }" : "=r"(a) : "l"(p));
    return a;
}

__device__ __forceinline__ void ldsm4(uint32_t* r, uint32_t addr) {
    asm volatile("ldmatrix.sync.aligned.m8n8.x4.shared.b16 {%0,%1,%2,%3}, [%4];"
                 : "=r"(r[0]), "=r"(r[1]), "=r"(r[2]), "=r"(r[3]) : "r"(addr));
}

__device__ __forceinline__ void mma_bf16(float* d, const uint32_t* a, uint32_t b0, uint32_t b1) {
    asm volatile("mma.sync.aligned.m16n8k16.row.col.f32.bf16.bf16.f32 "
                 "{%0,%1,%2,%3}, {%4,%5,%6,%7}, {%8,%9}, {%0,%1,%2,%3};"
                 : "+f"(d[0]), "+f"(d[1]), "+f"(d[2]), "+f"(d[3])
                 : "r"(a[0]), "r"(a[1]), "r"(a[2]), "r"(a[3]), "r"(b0), "r"(b1));
}

__device__ __forceinline__ void split_pack(float a, float b, uint32_t& hi, uint32_t& lo) {
    __nv_bfloat16 ha = __float2bfloat16(a);
    __nv_bfloat16 hb = __float2bfloat16(b);
    __nv_bfloat16 la = __float2bfloat16(a - __bfloat162float(ha));
    __nv_bfloat16 lb = __float2bfloat16(b - __bfloat162float(hb));
    __nv_bfloat162 hp = __nv_bfloat162(ha, hb);
    __nv_bfloat162 lp = __nv_bfloat162(la, lb);
    hi = *reinterpret_cast<uint32_t*>(&hp);
    lo = *reinterpret_cast<uint32_t*>(&lp);
}

// ============================================================================
// Kernel 0: split w fp32 -> bf16 hi/lo
// ============================================================================
__global__ __launch_bounds__(256) void split_w_kernel(const float4* __restrict__ src, int n4)
{
    int idx = blockIdx.x * 256 + threadIdx.x;
    if (idx >= n4) return;
    float4 v = src[idx];
    uint32_t h01, l01, h23, l23;
    split_pack(v.x, v.y, h01, l01);
    split_pack(v.z, v.w, h23, l23);
    ((uint2*)g_w_h)[idx] = make_uint2(h01, h23);
    ((uint2*)g_w_l)[idx] = make_uint2(l01, l23);
}

// ----------------------------------------------------------------------------
// smem layout (bytes): B_hi 32K | B_lo 32K | A_hi 8K | A_lo 8K = 80K
// ----------------------------------------------------------------------------
#define SB_H 0
#define SB_L 32768
#define SA_H 65536
#define SA_L 73728
#define SMEM_GEMM 81920

__device__ __forceinline__ uint32_t swz(int row, int colb) {
    return (uint32_t)(row * 128 + (colb ^ ((row & 7) << 4)));
}

// ============================================================================
// Kernel 1: hat2[s][b][m] = sum_k item[b,s,k] * w[s,m,k], bf16 split-2.
// One b-tile (64) x full m (256) per CTA; fused precision passes.
// grid = (BCHUNK/64, 50); b0 selects the chunk.
// ============================================================================
__global__ __launch_bounds__(256, 2) void hat_mma_kernel(
    const float* __restrict__ item, int b0)
{
    extern __shared__ __align__(1024) char smem[];
    const uint32_t sb = smem_u32(smem);
    const int t    = threadIdx.x;
    const int lane = t & 31;
    const int wid  = t >> 5;
    const int wy   = wid >> 2;     // 0..1
    const int wx   = wid & 3;      // 0..3
    const int bt   = (b0 >> 6) + blockIdx.x;   // global b-tile index
    const int s    = blockIdx.y;

    // ---- A: 64 rows x 64 k fp32 -> split bf16 hi/lo into smem
    {
        const float* ag = item + (size_t)(bt * 64) * (S_ * E_) + (size_t)s * E_;
        #pragma unroll
        for (int c = 0; c < 4; ++c) {
            int f4 = t + c * 256;
            int r  = f4 >> 4;
            int k0 = (f4 & 15) * 4;
            float4 v = *(const float4*)(ag + (size_t)r * (S_ * E_) + k0);
            uint32_t h01, l01, h23, l23;
            split_pack(v.x, v.y, h01, l01);
            split_pack(v.z, v.w, h23, l23);
            uint32_t off = swz(r, k0 * 2);
            *(uint2*)(smem + SA_H + off) = make_uint2(h01, h23);
            *(uint2*)(smem + SA_L + off) = make_uint2(l01, l23);
        }
    }
    // ---- B: 256 rows x 64 k, pre-split bf16 (L2-resident)
    {
        const __nv_bfloat16* bh = g_w_h + (size_t)s * (I_ * E_ * E_);
        const __nv_bfloat16* bl = g_w_l + (size_t)s * (I_ * E_ * E_);
        #pragma unroll
        for (int c = 0; c < 8; ++c) {
            int f  = t + c * 256;
            int r  = f >> 3;
            int ch = f & 7;
            uint32_t off = swz(r, ch * 16);
            size_t g = (size_t)r * E_ + ch * 8;
            *(uint4*)(smem + SB_H + off) = *(const uint4*)(bh + g);
            *(uint4*)(smem + SB_L + off) = *(const uint4*)(bl + g);
        }
    }
    __syncthreads();

    float acc[2][8][4];
    #pragma unroll
    for (int mi = 0; mi < 2; ++mi)
        #pragma unroll
        for (int j = 0; j < 8; ++j)
            #pragma unroll
            for (int q = 0; q < 4; ++q) acc[mi][j][q] = 0.0f;

    const int rsub = (lane & 7) + (lane & 8);
    const int csub = (lane >> 4) << 4;

    // fused passes: hh + lh off B_hi, then hl off B_lo. 12 ldsm, 48 mma.
    #pragma unroll
    for (int ks = 0; ks < 4; ++ks) {
        const int kb = ks * 32 + csub;
        uint32_t af_h[2][4], af_l[2][4], bf[4][4];
        #pragma unroll
        for (int mi = 0; mi < 2; ++mi) {
            int r = wy * 32 + mi * 16 + rsub;
            ldsm4(af_h[mi], sb + SA_H + swz(r, kb));
            ldsm4(af_l[mi], sb + SA_L + swz(r, kb));
        }
        #pragma unroll
        for (int nb = 0; nb < 4; ++nb) {
            int n = wx * 64 + nb * 16 + rsub;
            ldsm4(bf[nb], sb + SB_H + swz(n, kb));
        }
        #pragma unroll
        for (int mi = 0; mi < 2; ++mi)
            #pragma unroll
            for (int j = 0; j < 8; ++j) {
                mma_bf16(acc[mi][j], af_h[mi], bf[j >> 1][j & 1], bf[j >> 1][2 + (j & 1)]);
                mma_bf16(acc[mi][j], af_l[mi], bf[j >> 1][j & 1], bf[j >> 1][2 + (j & 1)]);
            }
        #pragma unroll
        for (int nb = 0; nb < 4; ++nb) {
            int n = wx * 64 + nb * 16 + rsub;
            ldsm4(bf[nb], sb + SB_L + swz(n, kb));
        }
        #pragma unroll
        for (int mi = 0; mi < 2; ++mi)
            #pragma unroll
            for (int j = 0; j < 8; ++j)
                mma_bf16(acc[mi][j], af_h[mi], bf[j >> 1][j & 1], bf[j >> 1][2 + (j & 1)]);
    }

    // stores: layout (s, b, m) — CTA block contiguous 64 KB
    const size_t base = ((size_t)s * B_ + bt * 64) * 256;
    #pragma unroll
    for (int mi = 0; mi < 2; ++mi) {
        int row = wy * 32 + mi * 16 + (lane >> 2);
        #pragma unroll
        for (int j = 0; j < 8; ++j) {
            int m = wx * 64 + j * 8 + (lane & 3) * 2;
            size_t off = base + (size_t)row * 256 + m;
            *(float2*)(g_hat + off)           = make_float2(acc[mi][j][0], acc[mi][j][1]);
            *(float2*)(g_hat + off + 8 * 256) = make_float2(acc[mi][j][2], acc[mi][j][3]);
        }
    }
}

// ============================================================================
// Kernel 2: dynamic routing. 64 threads per (b, i); b0 selects chunk
// (hat chunk expected L2-resident from the just-finished GEMM chunk).
// ============================================================================
__device__ __forceinline__ float wred_max(float v) {
    #pragma unroll
    for (int o = 16; o > 0; o >>= 1) v = fmaxf(v, __shfl_xor_sync(0xffffffffu, v, o));
    return v;
}
__device__ __forceinline__ float wred_sum(float v) {
    #pragma unroll
    for (int o = 16; o > 0; o >>= 1) v += __shfl_xor_sync(0xffffffffu, v, o);
    return v;
}

__global__ __launch_bounds__(64) void routing_kernel(
    const int* __restrict__ mask, float* __restrict__ out, int b0)
{
    __shared__ __align__(16) float hat_sm[S_ * 68];
    __shared__ float sw_sm[64];
    __shared__ __align__(16) float cap_sm[64];
    __shared__ float red_sm[4];

    const int bi   = blockIdx.x;
    const int b    = b0 + (bi >> 2);
    const int i    = bi & 3;
    const int t    = threadIdx.x;
    const int wid  = t >> 5;
    const int lane = t & 31;

    const float mk = (t < S_ && mask[b * S_ + t] != 0) ? 1.0f : 0.0f;

    const size_t sstride = (size_t)B_ * 256;
    const float* hg = g_hat + (size_t)b * 256 + i * 64 + t;

    float h[S_];
    #pragma unroll
    for (int s = 0; s < S_; ++s) {
        h[s] = hg[(size_t)s * sstride];
        hat_sm[s * 68 + t] = h[s];
    }

    float cw = 0.0f, cap = 0.0f;
    __syncthreads();

    #pragma unroll
    for (int it = 0; it < 3; ++it) {
        float x = (t < S_) ? cw : -1e30f;
        float wm = wred_max(x);
        if (lane == 0) red_sm[wid] = wm;
        __syncthreads();
        float mx = fmaxf(red_sm[0], red_sm[1]);
        float ex = (t < S_) ? __expf(x - mx) : 0.0f;
        float ws = wred_sum(ex);
        if (lane == 0) red_sm[2 + wid] = ws;
        __syncthreads();
        float inv = 1.0f / (red_sm[2] + red_sm[3]);
        sw_sm[t] = ex * inv * mk;
        __syncthreads();

        float c0 = 0.0f, c1 = 0.0f;
        #pragma unroll
        for (int s = 0; s < S_ - 1; s += 2) {
            c0 = fmaf(sw_sm[s],     h[s],     c0);
            c1 = fmaf(sw_sm[s + 1], h[s + 1], c1);
        }
        float c = c0 + c1;

        float ns = wred_sum(c * c);
        if (lane == 0) red_sm[wid] = ns;
        __syncthreads();
        float n = red_sm[0] + red_sm[1];
        float scale = (n / (1.0f + n)) * rsqrtf(n + 1e-9f);
        cap = c * scale;

        if (it < 2) {
            cap_sm[t] = cap;
            __syncthreads();
            if (t < S_) {
                const float4* h4 = (const float4*)&hat_sm[t * 68];
                const float4* c4 = (const float4*)cap_sm;
                float d0 = 0.0f, d1 = 0.0f;
                #pragma unroll
                for (int e4 = 0; e4 < 16; e4 += 2) {
                    float4 hv = h4[e4], cv = c4[e4];
                    d0 = fmaf(hv.x, cv.x, d0); d0 = fmaf(hv.y, cv.y, d0);
                    d0 = fmaf(hv.z, cv.z, d0); d0 = fmaf(hv.w, cv.w, d0);
                    float4 hv2 = h4[e4 + 1], cv2 = c4[e4 + 1];
                    d1 = fmaf(hv2.x, cv2.x, d1); d1 = fmaf(hv2.y, cv2.y, d1);
                    d1 = fmaf(hv2.z, cv2.z, d1); d1 = fmaf(hv2.w, cv2.w, d1);
                }
                cw += d0 + d1;
            }
        }
    }

    out[((size_t)b * I_ + i) * E_ + t] = cap;
}

extern "C" void kernel_launch(void* const* d_in, const int* in_sizes, int n_in,
                              void* d_out, int out_size)
{
    const float* item = (const float*)d_in[0];   // (4096, 50, 64) fp32
    const int*   mask = (const int*)d_in[1];     // (4096, 50) int32
    const float* w    = (const float*)d_in[2];   // (1, 50, 256, 64) fp32
    float* out = (float*)d_out;                  // (4096, 4, 64) fp32

    const int w4 = (int)(W_N / 4);
    split_w_kernel<<<(w4 + 255) / 256, 256>>>((const float4*)w, w4);

    cudaFuncSetAttribute(hat_mma_kernel, cudaFuncAttributeMaxDynamicSharedMemorySize,
                         SMEM_GEMM);

    // chunked producer/consumer: per 1024-b chunk, GEMM then routing,
    // so routing's hat reads hit L2 (52.4 MB chunk << 126 MB L2).
    for (int c = 0; c < NCHUNK; ++c) {
        int b0 = c * BCHUNK;
        hat_mma_kernel<<<dim3(BCHUNK / 64, 50), 256, SMEM_GEMM>>>(item, b0);
        routing_kernel<<<BCHUNK * I_, 64>>>(mask, out, b0);
    }
}

// round 17
// speedup vs baseline: 1.1525x; 1.1525x over previous
#include <cuda_runtime.h>
#include <cuda_bf16.h>
#include <math.h>
#include <stdint.h>

#define B_ 4096
#define S_ 50
#define I_ 4
#define E_ 64

// hat scratch, layout (S, B, I*E): hat2[s][b][m] — fp32, 209.7 MB
__device__ __align__(256) float g_hat[(size_t)S_ * B_ * I_ * E_];

// pre-split bf16 hi/lo copies of w
#define W_N ((size_t)S_ * I_ * E_ * E_)  // 819,200
__device__ __align__(256) __nv_bfloat16 g_w_h[W_N];
__device__ __align__(256) __nv_bfloat16 g_w_l[W_N];

// ============================================================================
// helpers
// ============================================================================
__device__ __forceinline__ uint32_t smem_u32(const void* p) {
    uint32_t a;
    asm("{ .reg .u64 t; cvta.to.shared.u64 t, %1; cvt.u32.u64 %0, t; }" : "=r"(a) : "l"(p));
    return a;
}

__device__ __forceinline__ void ldsm4(uint32_t* r, uint32_t addr) {
    asm volatile("ldmatrix.sync.aligned.m8n8.x4.shared.b16 {%0,%1,%2,%3}, [%4];"
                 : "=r"(r[0]), "=r"(r[1]), "=r"(r[2]), "=r"(r[3]) : "r"(addr));
}

__device__ __forceinline__ void mma_bf16(float* d, const uint32_t* a, uint32_t b0, uint32_t b1) {
    asm volatile("mma.sync.aligned.m16n8k16.row.col.f32.bf16.bf16.f32 "
                 "{%0,%1,%2,%3}, {%4,%5,%6,%7}, {%8,%9}, {%0,%1,%2,%3};"
                 : "+f"(d[0]), "+f"(d[1]), "+f"(d[2]), "+f"(d[3])
                 : "r"(a[0]), "r"(a[1]), "r"(a[2]), "r"(a[3]), "r"(b0), "r"(b1));
}

__device__ __forceinline__ void split_pack(float a, float b, uint32_t& hi, uint32_t& lo) {
    __nv_bfloat16 ha = __float2bfloat16(a);
    __nv_bfloat16 hb = __float2bfloat16(b);
    __nv_bfloat16 la = __float2bfloat16(a - __bfloat162float(ha));
    __nv_bfloat16 lb = __float2bfloat16(b - __bfloat162float(hb));
    __nv_bfloat162 hp = __nv_bfloat162(ha, hb);
    __nv_bfloat162 lp = __nv_bfloat162(la, lb);
    hi = *reinterpret_cast<uint32_t*>(&hp);
    lo = *reinterpret_cast<uint32_t*>(&lp);
}

// ============================================================================
// Kernel 0: split w fp32 -> bf16 hi/lo
// ============================================================================
__global__ __launch_bounds__(256) void split_w_kernel(const float4* __restrict__ src, int n4)
{
    int idx = blockIdx.x * 256 + threadIdx.x;
    if (idx >= n4) return;
    float4 v = src[idx];
    uint32_t h01, l01, h23, l23;
    split_pack(v.x, v.y, h01, l01);
    split_pack(v.z, v.w, h23, l23);
    ((uint2*)g_w_h)[idx] = make_uint2(h01, h23);
    ((uint2*)g_w_l)[idx] = make_uint2(l01, l23);
}

// ----------------------------------------------------------------------------
// GEMM smem layout (bytes): B_hi 32K | B_lo 32K | A_hi 8K | A_lo 8K = 80K
// ----------------------------------------------------------------------------
#define SB_H 0
#define SB_L 32768
#define SA_H 65536
#define SA_L 73728
#define SMEM_GEMM 81920

__device__ __forceinline__ uint32_t swz(int row, int colb) {
    return (uint32_t)(row * 128 + (colb ^ ((row & 7) << 4)));
}

// ============================================================================
// Kernel 1 (round-11 winner): hat2[s][b][m], bf16 split-2, persistent over
// 4 b-tiles, fused precision passes. grid = (16, 50)
// ============================================================================
__global__ __launch_bounds__(256, 2) void hat_mma_kernel(
    const float* __restrict__ item)   // (B, S, E) fp32
{
    extern __shared__ __align__(1024) char smem[];
    const uint32_t sb = smem_u32(smem);
    const int t    = threadIdx.x;
    const int lane = t & 31;
    const int wid  = t >> 5;
    const int wy   = wid >> 2;     // 0..1
    const int wx   = wid & 3;      // 0..3
    const int btg  = blockIdx.x;   // 0..15
    const int s    = blockIdx.y;

    int ar[4], ak[4];
    #pragma unroll
    for (int c = 0; c < 4; ++c) {
        int f4 = t + c * 256;
        ar[c] = f4 >> 4;
        ak[c] = (f4 & 15) * 4;
    }

    // ---- B loaded ONCE
    {
        const __nv_bfloat16* bh = g_w_h + (size_t)s * (I_ * E_ * E_);
        const __nv_bfloat16* bl = g_w_l + (size_t)s * (I_ * E_ * E_);
        #pragma unroll
        for (int c = 0; c < 8; ++c) {
            int f  = t + c * 256;
            int r  = f >> 3;
            int ch = f & 7;
            uint32_t off = swz(r, ch * 16);
            size_t g = (size_t)r * E_ + ch * 8;
            *(uint4*)(smem + SB_H + off) = *(const uint4*)(bh + g);
            *(uint4*)(smem + SB_L + off) = *(const uint4*)(bl + g);
        }
    }

    float4 areg[4];
    {
        const float* ag = item + (size_t)(btg * 4 * 64) * (S_ * E_) + (size_t)s * E_;
        #pragma unroll
        for (int c = 0; c < 4; ++c)
            areg[c] = *(const float4*)(ag + (size_t)ar[c] * (S_ * E_) + ak[c]);
    }

    const int rsub = (lane & 7) + (lane & 8);
    const int csub = (lane >> 4) << 4;

    #pragma unroll
    for (int it = 0; it < 4; ++it) {
        const int bt = btg * 4 + it;

        #pragma unroll
        for (int c = 0; c < 4; ++c) {
            uint32_t h01, l01, h23, l23;
            split_pack(areg[c].x, areg[c].y, h01, l01);
            split_pack(areg[c].z, areg[c].w, h23, l23);
            uint32_t off = swz(ar[c], ak[c] * 2);
            *(uint2*)(smem + SA_H + off) = make_uint2(h01, h23);
            *(uint2*)(smem + SA_L + off) = make_uint2(l01, l23);
        }
        if (it < 3) {
            const float* ag = item + (size_t)((bt + 1) * 64) * (S_ * E_) + (size_t)s * E_;
            #pragma unroll
            for (int c = 0; c < 4; ++c)
                areg[c] = *(const float4*)(ag + (size_t)ar[c] * (S_ * E_) + ak[c]);
        }
        __syncthreads();

        float acc[2][8][4];
        #pragma unroll
        for (int mi = 0; mi < 2; ++mi)
            #pragma unroll
            for (int j = 0; j < 8; ++j)
                #pragma unroll
                for (int q = 0; q < 4; ++q) acc[mi][j][q] = 0.0f;

        #pragma unroll
        for (int ks = 0; ks < 4; ++ks) {
            const int kb = ks * 32 + csub;
            uint32_t af_h[2][4], af_l[2][4], bf[4][4];
            #pragma unroll
            for (int mi = 0; mi < 2; ++mi) {
                int r = wy * 32 + mi * 16 + rsub;
                ldsm4(af_h[mi], sb + SA_H + swz(r, kb));
                ldsm4(af_l[mi], sb + SA_L + swz(r, kb));
            }
            #pragma unroll
            for (int nb = 0; nb < 4; ++nb) {
                int n = wx * 64 + nb * 16 + rsub;
                ldsm4(bf[nb], sb + SB_H + swz(n, kb));
            }
            #pragma unroll
            for (int mi = 0; mi < 2; ++mi)
                #pragma unroll
                for (int j = 0; j < 8; ++j) {
                    mma_bf16(acc[mi][j], af_h[mi], bf[j >> 1][j & 1], bf[j >> 1][2 + (j & 1)]);
                    mma_bf16(acc[mi][j], af_l[mi], bf[j >> 1][j & 1], bf[j >> 1][2 + (j & 1)]);
                }
            #pragma unroll
            for (int nb = 0; nb < 4; ++nb) {
                int n = wx * 64 + nb * 16 + rsub;
                ldsm4(bf[nb], sb + SB_L + swz(n, kb));
            }
            #pragma unroll
            for (int mi = 0; mi < 2; ++mi)
                #pragma unroll
                for (int j = 0; j < 8; ++j)
                    mma_bf16(acc[mi][j], af_h[mi], bf[j >> 1][j & 1], bf[j >> 1][2 + (j & 1)]);
        }

        const size_t base = ((size_t)s * B_ + bt * 64) * 256;
        #pragma unroll
        for (int mi = 0; mi < 2; ++mi) {
            int row = wy * 32 + mi * 16 + (lane >> 2);
            #pragma unroll
            for (int j = 0; j < 8; ++j) {
                int m = wx * 64 + j * 8 + (lane & 3) * 2;
                size_t off = base + (size_t)row * 256 + m;
                *(float2*)(g_hat + off)           = make_float2(acc[mi][j][0], acc[mi][j][1]);
                *(float2*)(g_hat + off + 8 * 256) = make_float2(acc[mi][j][2], acc[mi][j][3]);
            }
        }
        __syncthreads();
    }
}

// ============================================================================
// Kernel 2: dynamic routing. 128 threads per (b, interest-pair): interests
// {2*ip, 2*ip+1}. hat reads are 512 B contiguous per (s,b,pair). Static smem
// only (26.4 KB hat_sm). grid = B_*2.
// ============================================================================
#define HSTRIDE 132   // 128 + 4 pad floats

__global__ __launch_bounds__(128) void routing_kernel(
    const int* __restrict__ mask,    // (B, S)
    float* __restrict__ out)         // (B, I, E)
{
    __shared__ __align__(16) float hat_sm[S_ * HSTRIDE];   // 26.4 KB
    __shared__ float sw_sm[128];     // [ii_local][s]
    __shared__ __align__(16) float cap_sm[128];   // [ii_local][e]
    __shared__ float red_sm[2][2];
    __shared__ float red2_sm[2][2];

    const int cta  = blockIdx.x;
    const int b    = cta >> 1;
    const int ip   = cta & 1;         // interest pair 0 or 1
    const int t    = threadIdx.x;     // 0..127
    const int il   = t >> 6;          // local interest 0..1
    const int x    = t & 63;          // e for cap, s for softmax/delta
    const int wg   = (t >> 5) & 1;    // warp within interest group
    const int lane = t & 31;

    const float mk = (x < S_ && mask[b * S_ + x] != 0) ? 1.0f : 0.0f;

    // hat2[s][b][m]: this CTA owns columns m = ip*128 + t. 512 B contiguous.
    const size_t sstride = (size_t)B_ * 256;
    const float* hg = g_hat + (size_t)b * 256 + ip * 128 + t;

    float h[S_];
    #pragma unroll
    for (int s = 0; s < S_; ++s) {
        h[s] = hg[(size_t)s * sstride];
        hat_sm[s * HSTRIDE + t] = h[s];
    }

    float cw = 0.0f, cap = 0.0f;
    __syncthreads();

    #pragma unroll
    for (int it = 0; it < 3; ++it) {
        // per-interest softmax over 50 s (max-subtracted), masked, no renorm
        float v = (x < S_) ? cw : -1e30f;
        float wm = v;
        #pragma unroll
        for (int o = 16; o > 0; o >>= 1) wm = fmaxf(wm, __shfl_xor_sync(0xffffffffu, wm, o));
        if (lane == 0) red_sm[il][wg] = wm;
        __syncthreads();                                     // sync 1
        float mx = fmaxf(red_sm[il][0], red_sm[il][1]);
        float ex = (x < S_) ? __expf(v - mx) : 0.0f;
        float ws = ex;
        #pragma unroll
        for (int o = 16; o > 0; o >>= 1) ws += __shfl_xor_sync(0xffffffffu, ws, o);
        if (lane == 0) red2_sm[il][wg] = ws;
        __syncthreads();                                     // sync 2
        float inv = 1.0f / (red2_sm[il][0] + red2_sm[il][1]);
        sw_sm[t] = ex * inv * mk;     // [il][s]; s >= 50 never read
        __syncthreads();                                     // sync 3

        // cap[il][e=x] = sum_s sw[il][s] * h[s]
        const float* swp = &sw_sm[il * 64];
        float c0 = 0.0f, c1 = 0.0f;
        #pragma unroll
        for (int s = 0; s < S_ - 1; s += 2) {
            c0 = fmaf(swp[s],     h[s],     c0);
            c1 = fmaf(swp[s + 1], h[s + 1], c1);
        }
        float c = c0 + c1;

        // squash per interest (64-thread = 2-warp reduction)
        float ns = c * c;
        #pragma unroll
        for (int o = 16; o > 0; o >>= 1) ns += __shfl_xor_sync(0xffffffffu, ns, o);
        if (lane == 0) red_sm[il][wg] = ns;
        __syncthreads();                                     // sync 4
        float n = red_sm[il][0] + red_sm[il][1];
        float scale = (n / (1.0f + n)) * rsqrtf(n + 1e-9f);
        cap = c * scale;

        if (it < 2) {
            cap_sm[t] = cap;
            __syncthreads();                                 // sync 5
            // delta[il][s=x] = sum_e hat[s][il*64+e] * cap[il][e]
            if (x < S_) {
                const float4* h4 = (const float4*)&hat_sm[x * HSTRIDE + il * 64];
                const float4* c4 = (const float4*)&cap_sm[il * 64];
                float d0 = 0.0f, d1 = 0.0f;
                #pragma unroll
                for (int e4 = 0; e4 < 16; e4 += 2) {
                    float4 hv = h4[e4], cv = c4[e4];
                    d0 = fmaf(hv.x, cv.x, d0); d0 = fmaf(hv.y, cv.y, d0);
                    d0 = fmaf(hv.z, cv.z, d0); d0 = fmaf(hv.w, cv.w, d0);
                    float4 hv2 = h4[e4 + 1], cv2 = c4[e4 + 1];
                    d1 = fmaf(hv2.x, cv2.x, d1); d1 = fmaf(hv2.y, cv2.y, d1);
                    d1 = fmaf(hv2.z, cv2.z, d1); d1 = fmaf(hv2.w, cv2.w, d1);
                }
                cw += d0 + d1;
            }
            // end-of-delta sync elided: rewrites fenced by next iter's syncs
        }
    }

    // out[b][i][e]: 512 B contiguous per CTA
    out[(size_t)b * 256 + ip * 128 + t] = cap;
}

extern "C" void kernel_launch(void* const* d_in, const int* in_sizes, int n_in,
                              void* d_out, int out_size)
{
    const float* item = (const float*)d_in[0];   // (4096, 50, 64) fp32
    const int*   mask = (const int*)d_in[1];     // (4096, 50) int32
    const float* w    = (const float*)d_in[2];   // (1, 50, 256, 64) fp32
    float* out = (float*)d_out;                  // (4096, 4, 64) fp32

    const int w4 = (int)(W_N / 4);
    split_w_kernel<<<(w4 + 255) / 256, 256>>>((const float4*)w, w4);

    cudaFuncSetAttribute(hat_mma_kernel, cudaFuncAttributeMaxDynamicSharedMemorySize,
                         SMEM_GEMM);
    hat_mma_kernel<<<dim3(16, 50), 256, SMEM_GEMM>>>(item);

    routing_kernel<<<B_ * 2, 128>>>(mask, out);
}